// round 3
// baseline (speedup 1.0000x reference)
#include <cuda_runtime.h>
#include <cuda_bf16.h>
#include <cstdint>

#define BS 16
#define SP_IN 512
#define SP_OUT 256
#define DN_IN 128
#define DN_OUT 128
#define N_STK 256
#define N_STK_PNT 32
#define N_BEF 512
#define C_COOR 128

// ---------------- scratch (device globals; no allocation allowed) ----------------
__device__ float g_coorT[BS * C_COOR * N_STK];        // [b][c][m]
__device__ float g_spT  [BS * N_STK * SP_IN];         // [b][m][c]
__device__ float g_wspT [SP_IN * SP_OUT];             // [c][o]
__device__ float g_normM[BS * N_STK];
__device__ float g_normB[BS * N_BEF];
__device__ int2   g_nn[BS * N_BEF];
__device__ float2 g_wt[BS * N_BEF];

// ---------------- helpers ----------------
__device__ __forceinline__ unsigned long long pack2(float a, float b) {
    unsigned long long r;
    asm("mov.b64 %0, {%1, %2};" : "=l"(r) : "f"(a), "f"(b));
    return r;
}
__device__ __forceinline__ float2 unpack2f(unsigned long long v) {
    float2 r;
    asm("mov.b64 {%0, %1}, %2;" : "=f"(r.x), "=f"(r.y) : "l"(v));
    return r;
}
// packed dual fp32 FMA: acc = a*b + acc (both lanes)
__device__ __forceinline__ void ffma2(unsigned long long &acc, unsigned long long a, unsigned long long b) {
    asm("fma.rn.f32x2 %0, %1, %2, %0;" : "+l"(acc) : "l"(a), "l"(b));
}
__device__ __forceinline__ unsigned mono(float f) {
    unsigned u = __float_as_uint(f);
    return (u & 0x80000000u) ? ~u : (u | 0x80000000u);
}
__device__ __forceinline__ float invmono(unsigned u) {
    unsigned v = (u & 0x80000000u) ? (u & 0x7FFFFFFFu) : ~u;
    return __uint_as_float(v);
}
// tanh-approx GELU (jax.nn.gelu default), NaN-safe for large |x|
__device__ __forceinline__ float gelu_tanh(float x) {
    float g = 0.7978845608028654f * x * fmaf(0.044715f, x * x, 1.0f);
    float e = __expf(2.0f * g);
    float th = 1.0f - 2.0f / (e + 1.0f);
    return 0.5f * x * (1.0f + th);
}
#define INV_SQRT_BN 0.99999500003749973f  // 1/sqrt(1+1e-5)

// ---------------- per-batch transpose [R,C] -> [C,R] ----------------
template<int R, int C, int WHICH>
__global__ void k_transpose(const float* __restrict__ src) {
    float* dstbase = (WHICH == 0) ? g_coorT : (WHICH == 1) ? g_spT : g_wspT;
    __shared__ float tile[32][33];
    int b = blockIdx.z;
    const float* s = src + (size_t)b * R * C;
    float* d = dstbase + (size_t)b * R * C;
    int r0 = blockIdx.y * 32, c0 = blockIdx.x * 32;
#pragma unroll
    for (int k = 0; k < 32; k += 8)
        tile[threadIdx.y + k][threadIdx.x] = s[(size_t)(r0 + threadIdx.y + k) * C + c0 + threadIdx.x];
    __syncthreads();
#pragma unroll
    for (int k = 0; k < 32; k += 8)
        d[(size_t)(c0 + threadIdx.y + k) * R + r0 + threadIdx.x] = tile[threadIdx.x][threadIdx.y + k];
}

// ---------------- row sum-of-squares (rows of 128 floats) ----------------
template<int WHICH>  // 0 -> g_normM, 1 -> g_normB
__global__ void k_norm128(const float* __restrict__ src, int rows) {
    float* dst = WHICH ? g_normB : g_normM;
    int warp = (blockIdx.x * blockDim.x + threadIdx.x) >> 5;
    int lane = threadIdx.x & 31;
    if (warp >= rows) return;
    float4 v = ((const float4*)(src + (size_t)warp * 128))[lane];
    float s = v.x * v.x + v.y * v.y + v.z * v.z + v.w * v.w;
#pragma unroll
    for (int off = 16; off; off >>= 1) s += __shfl_xor_sync(0xffffffffu, s, off);
    if (!lane) dst[warp] = s;
}

// ---------------- distances + top-2 + weights ----------------
__global__ __launch_bounds__(256) void k_topk(const float* __restrict__ bef) {
    __shared__ float befs[16 * 128];
    __shared__ unsigned long long red[8];
    __shared__ unsigned long long s_win;
    int n0 = blockIdx.x * 16, b = blockIdx.y;
    int tid = threadIdx.x;
    for (int idx = tid; idx < 16 * 128; idx += 256)
        befs[idx] = bef[((size_t)b * N_BEF + n0) * 128 + idx];
    __syncthreads();

    int m = tid;  // 256 threads == 256 candidate strokes
    float acc[16];
#pragma unroll
    for (int j = 0; j < 16; j++) acc[j] = 0.0f;
    const float* cT = g_coorT + (size_t)b * C_COOR * N_STK + m;
    for (int cb = 0; cb < 128; cb += 32) {          // chunked for lower rounding error
        float part[16];
#pragma unroll
        for (int j = 0; j < 16; j++) part[j] = 0.0f;
        for (int c0 = cb; c0 < cb + 32; c0 += 4) {
            float v0 = cT[(c0 + 0) * N_STK];
            float v1 = cT[(c0 + 1) * N_STK];
            float v2 = cT[(c0 + 2) * N_STK];
            float v3 = cT[(c0 + 3) * N_STK];
#pragma unroll
            for (int j = 0; j < 16; j++) {
                float4 bf = *(const float4*)&befs[j * 128 + c0];
                part[j] = fmaf(bf.x, v0, part[j]);
                part[j] = fmaf(bf.y, v1, part[j]);
                part[j] = fmaf(bf.z, v2, part[j]);
                part[j] = fmaf(bf.w, v3, part[j]);
            }
        }
#pragma unroll
        for (int j = 0; j < 16; j++) acc[j] += part[j];
    }
    float nm = g_normM[b * N_STK + m];
    int lane = tid & 31, wid = tid >> 5;
    for (int j = 0; j < 16; j++) {
        float d2v = g_normB[b * N_BEF + n0 + j] + nm - 2.0f * acc[j];
        unsigned long long key = ((unsigned long long)mono(d2v) << 8) | (unsigned)m;
        unsigned long long k = key;
#pragma unroll
        for (int off = 16; off; off >>= 1) {
            unsigned long long o = __shfl_xor_sync(0xffffffffu, k, off);
            if (o < k) k = o;
        }
        if (lane == 0) red[wid] = k;
        __syncthreads();
        if (tid == 0) {
            unsigned long long mn = red[0];
#pragma unroll
            for (int w = 1; w < 8; w++) if (red[w] < mn) mn = red[w];
            s_win = mn;
        }
        __syncthreads();
        unsigned long long win1 = s_win;
        k = (key == win1) ? 0xFFFFFFFFFFFFFFFFull : key;
#pragma unroll
        for (int off = 16; off; off >>= 1) {
            unsigned long long o = __shfl_xor_sync(0xffffffffu, k, off);
            if (o < k) k = o;
        }
        if (lane == 0) red[wid] = k;
        __syncthreads();
        if (tid == 0) {
            unsigned long long mn2 = red[0];
#pragma unroll
            for (int w = 1; w < 8; w++) if (red[w] < mn2) mn2 = red[w];
            float d0 = invmono((unsigned)(win1 >> 8));
            float d1 = invmono((unsigned)(mn2 >> 8));
            int i0 = (int)(win1 & 0xFF), i1 = (int)(mn2 & 0xFF);
            float r0 = 1.0f / (d0 + 1e-8f), r1 = 1.0f / (d1 + 1e-8f);
            float s = r0 + r1;
            g_nn[b * N_BEF + n0 + j] = make_int2(i0, i1);
            g_wt[b * N_BEF + n0 + j] = make_float2(r0 / s, r1 / s);
        }
        __syncthreads();
    }
}

// ---------------- sparse branch: gather+interp, GEMM, BN+GELU ----------------
__global__ __launch_bounds__(256) void k_sparse(const float* __restrict__ b_sp,
                                                const float* __restrict__ gam,
                                                const float* __restrict__ bet,
                                                float* __restrict__ out) {
    __shared__ float V[512 * 20];   // [c][j], stride 20 (16B-aligned rows)
    __shared__ int2 ii[16];
    __shared__ float2 ww[16];
    int n0 = blockIdx.x * 16, b = blockIdx.y, tid = threadIdx.x;
    if (tid < 16) {
        ii[tid] = g_nn[b * N_BEF + n0 + tid];
        ww[tid] = g_wt[b * N_BEF + n0 + tid];
    }
    __syncthreads();
    const float* sT = g_spT + (size_t)b * N_STK * SP_IN;
    for (int idx = tid; idx < 512 * 16; idx += 256) {
        int j = idx >> 9, c = idx & 511;
        int2 id = ii[j];
        float2 wt = ww[j];
        V[c * 20 + j] = wt.x * sT[(size_t)id.x * SP_IN + c] + wt.y * sT[(size_t)id.y * SP_IN + c];
    }
    __syncthreads();
    int o = tid;
    unsigned long long acc[8] = {0, 0, 0, 0, 0, 0, 0, 0};
#pragma unroll 4
    for (int c = 0; c < 512; c++) {
        float wv = g_wspT[c * SP_OUT + o];
        unsigned long long w2 = pack2(wv, wv);
        const ulonglong2* vr = (const ulonglong2*)&V[c * 20];
        ulonglong2 p0 = vr[0], p1 = vr[1], p2 = vr[2], p3 = vr[3];
        ffma2(acc[0], w2, p0.x); ffma2(acc[1], w2, p0.y);
        ffma2(acc[2], w2, p1.x); ffma2(acc[3], w2, p1.y);
        ffma2(acc[4], w2, p2.x); ffma2(acc[5], w2, p2.y);
        ffma2(acc[6], w2, p3.x); ffma2(acc[7], w2, p3.y);
    }
    float bias = b_sp[o];
    float sc = gam[o] * INV_SQRT_BN;
    float bt = bet[o];
    float res[16];
#pragma unroll
    for (int p = 0; p < 8; p++) {
        float2 f = unpack2f(acc[p]);
        res[2 * p]     = gelu_tanh(fmaf(f.x + bias, sc, bt));
        res[2 * p + 1] = gelu_tanh(fmaf(f.y + bias, sc, bt));
    }
    float* ob = out + ((size_t)b * SP_OUT + o) * N_BEF + n0;
#pragma unroll
    for (int q = 0; q < 4; q++)
        *(float4*)&ob[4 * q] = make_float4(res[4 * q], res[4 * q + 1], res[4 * q + 2], res[4 * q + 3]);
}

// ---------------- dense branch: interp + ConvT(k4,s2,p3) + BN + GELU ----------------
// T[c][l] (l=0..33) holds Dflat[b,c, clamp(32n-1+l, 0, 16383)].
// out[2L]   = sum_c W3*T[L]   + W1*T[L+1]
// out[2L+1] = sum_c W2*T[L+1] + W0*T[L+2],  L in 0..31 local, tap k = w_ct[c][o][k]
__global__ __launch_bounds__(256, 2) void k_dense(const float* __restrict__ dense,
                                                  const float* __restrict__ w_ct,
                                                  const float* __restrict__ b_ct,
                                                  const float* __restrict__ gam,
                                                  const float* __restrict__ bet,
                                                  float* __restrict__ out) {
    __shared__ float sm[128 * 36];  // row stride 36 floats (cols 0..33 valid)
    int n = blockIdx.x, b = blockIdx.y, tid = threadIdx.x;
    int base = b * N_BEF;
    int2 iM = g_nn[base + n];
    float2 wM = g_wt[base + n];
    const float* dB = dense + (size_t)b * DN_IN * N_STK * N_STK_PNT;

    // phase 1: interpolated tile
    {
        int warp = tid >> 5, p = tid & 31;
        for (int c = warp; c < 128; c += 8) {
            float v0 = dB[((size_t)c * N_STK + iM.x) * N_STK_PNT + p];
            float v1 = dB[((size_t)c * N_STK + iM.y) * N_STK_PNT + p];
            sm[c * 36 + 1 + p] = wM.x * v0 + wM.y * v1;
        }
    }
    if (tid < 128) {
        int c = tid;
        int jl = 32 * n - 1; if (jl < 0) jl = 0;
        int sL = jl >> 5, pL = jl & 31;
        int2 iL = g_nn[base + sL]; float2 wL = g_wt[base + sL];
        sm[c * 36] = wL.x * dB[((size_t)c * N_STK + iL.x) * N_STK_PNT + pL]
                   + wL.y * dB[((size_t)c * N_STK + iL.y) * N_STK_PNT + pL];
        int jr = 32 * n + 32; if (jr > 16383) jr = 16383;
        int sR = jr >> 5, pR = jr & 31;
        int2 iR = g_nn[base + sR]; float2 wR = g_wt[base + sR];
        sm[c * 36 + 33] = wR.x * dB[((size_t)c * N_STK + iR.x) * N_STK_PNT + pR]
                        + wR.y * dB[((size_t)c * N_STK + iR.y) * N_STK_PNT + pR];
    }
    __syncthreads();

    // phase 2: per-tap partial sums S_k over pair-packed columns (f32x2 FMAs)
    int o = tid & 127, h = tid >> 7, r0 = h << 4;
    unsigned long long a3[8], a1[9], a2[9], a0[8];
#pragma unroll
    for (int p = 0; p < 8; p++) { a3[p] = 0ull; a0[p] = 0ull; }
#pragma unroll
    for (int p = 0; p < 9; p++) { a1[p] = 0ull; a2[p] = 0ull; }
    const float4* w4 = (const float4*)w_ct;  // [c][o] -> 4 taps
#pragma unroll 2
    for (int c = 0; c < 128; c++) {
        float4 w = w4[c * 128 + o];
        unsigned long long w0p = pack2(w.x, w.x);
        unsigned long long w1p = pack2(w.y, w.y);
        unsigned long long w2p = pack2(w.z, w.z);
        unsigned long long w3p = pack2(w.w, w.w);
        const ulonglong2* dr = (const ulonglong2*)&sm[c * 36 + r0];
        ulonglong2 q0 = dr[0], q1 = dr[1], q2 = dr[2], q3 = dr[3], q4 = dr[4];
        unsigned long long d0 = q0.x, d1 = q0.y, d2 = q1.x, d3 = q1.y, d4 = q2.x;
        unsigned long long d5 = q2.y, d6 = q3.x, d7 = q3.y, d8 = q4.x;
        ffma2(a3[0], w3p, d0); ffma2(a3[1], w3p, d1); ffma2(a3[2], w3p, d2); ffma2(a3[3], w3p, d3);
        ffma2(a3[4], w3p, d4); ffma2(a3[5], w3p, d5); ffma2(a3[6], w3p, d6); ffma2(a3[7], w3p, d7);
        ffma2(a1[0], w1p, d0); ffma2(a1[1], w1p, d1); ffma2(a1[2], w1p, d2); ffma2(a1[3], w1p, d3);
        ffma2(a1[4], w1p, d4); ffma2(a1[5], w1p, d5); ffma2(a1[6], w1p, d6); ffma2(a1[7], w1p, d7);
        ffma2(a1[8], w1p, d8);
        ffma2(a2[0], w2p, d0); ffma2(a2[1], w2p, d1); ffma2(a2[2], w2p, d2); ffma2(a2[3], w2p, d3);
        ffma2(a2[4], w2p, d4); ffma2(a2[5], w2p, d5); ffma2(a2[6], w2p, d6); ffma2(a2[7], w2p, d7);
        ffma2(a2[8], w2p, d8);
        ffma2(a0[0], w0p, d1); ffma2(a0[1], w0p, d2); ffma2(a0[2], w0p, d3); ffma2(a0[3], w0p, d4);
        ffma2(a0[4], w0p, d5); ffma2(a0[5], w0p, d6); ffma2(a0[6], w0p, d7); ffma2(a0[7], w0p, d8);
    }

    // epilogue: combine taps, bias + BN + GELU, store
    float A3f[16], A1f[18], A2f[18], A0f[18];
#pragma unroll
    for (int p = 0; p < 8; p++) { float2 f = unpack2f(a3[p]); A3f[2 * p] = f.x; A3f[2 * p + 1] = f.y; }
#pragma unroll
    for (int p = 0; p < 9; p++) { float2 f = unpack2f(a1[p]); A1f[2 * p] = f.x; A1f[2 * p + 1] = f.y; }
#pragma unroll
    for (int p = 0; p < 9; p++) { float2 f = unpack2f(a2[p]); A2f[2 * p] = f.x; A2f[2 * p + 1] = f.y; }
#pragma unroll
    for (int p = 0; p < 8; p++) { float2 f = unpack2f(a0[p]); A0f[2 * p + 2] = f.x; A0f[2 * p + 3] = f.y; }
    float bias = b_ct[o];
    float sc = gam[o] * INV_SQRT_BN;
    float bt = bet[o];
    float res[32];
#pragma unroll
    for (int i = 0; i < 16; i++) {
        float e  = A3f[i] + A1f[i + 1];
        float od = A2f[i + 1] + A0f[i + 2];
        res[2 * i]     = gelu_tanh(fmaf(e + bias, sc, bt));
        res[2 * i + 1] = gelu_tanh(fmaf(od + bias, sc, bt));
    }
    float* ob = out + (((size_t)b * DN_OUT + o) * N_BEF + n) * 64 + 32 * h;
#pragma unroll
    for (int q = 0; q < 8; q++)
        *(float4*)&ob[4 * q] = make_float4(res[4 * q], res[4 * q + 1], res[4 * q + 2], res[4 * q + 3]);
}

// ---------------- launcher ----------------
extern "C" void kernel_launch(void* const* d_in, const int* in_sizes, int n_in,
                              void* d_out, int out_size) {
    const float* sparse_fea = (const float*)d_in[0];
    const float* dense_fea  = (const float*)d_in[1];
    const float* stk_coor   = (const float*)d_in[2];
    const float* stk_bef    = (const float*)d_in[3];
    const float* w_sp   = (const float*)d_in[4];
    const float* b_sp   = (const float*)d_in[5];
    const float* gam_sp = (const float*)d_in[6];
    const float* bet_sp = (const float*)d_in[7];
    const float* w_ct   = (const float*)d_in[8];
    const float* b_ct   = (const float*)d_in[9];
    const float* gam_dn = (const float*)d_in[10];
    const float* bet_dn = (const float*)d_in[11];
    float* out_sp = (float*)d_out;
    float* out_dn = out_sp + (size_t)BS * SP_OUT * N_BEF;

    k_transpose<256, 128, 0><<<dim3(4, 8, 16), dim3(32, 8)>>>(stk_coor);
    k_transpose<512, 256, 1><<<dim3(8, 16, 16), dim3(32, 8)>>>(sparse_fea);
    k_transpose<256, 512, 2><<<dim3(16, 8, 1), dim3(32, 8)>>>(w_sp);
    k_norm128<0><<<512, 256>>>(stk_coor, BS * N_STK);
    k_norm128<1><<<1024, 256>>>(stk_bef, BS * N_BEF);
    k_topk<<<dim3(32, 16), 256>>>(stk_bef);
    k_sparse<<<dim3(32, 16), 256>>>(b_sp, gam_sp, bet_sp, out_sp);
    k_dense<<<dim3(512, 16), 256>>>(dense_fea, w_ct, b_ct, gam_dn, bet_dn, out_dn);
}

// round 5
// speedup vs baseline: 1.6359x; 1.6359x over previous
#include <cuda_runtime.h>
#include <cstdint>

#define BS 16
#define SP_IN 512
#define SP_OUT 256
#define DN_IN 128
#define N_STK 256
#define N_BEF 512
#define INV_SQRT_BN 0.99999500003749973f

// ---- scratch ----
__device__ float g_coorT[BS * 128 * N_STK];
__device__ float g_spT[BS * N_STK * SP_IN];
__device__ float g_wspT[SP_IN * SP_OUT];
__device__ float g_normM[BS * N_STK];
__device__ float g_normB[BS * N_BEF];
__device__ int2   g_nn[BS * N_BEF];
__device__ float2 g_wt[BS * N_BEF];
__device__ float g_Dp[(size_t)BS * 16386 * 128];   // [b][j=0..16385][c]; Dp[r]=D[r-1] clamped
__device__ float g_Afrag[2 * 32768];               // fragment-ordered tf32 A images (par 0/1)

// ---- helpers ----
__device__ __forceinline__ unsigned long long pack2(float a, float b) {
    unsigned long long r; asm("mov.b64 %0, {%1, %2};" : "=l"(r) : "f"(a), "f"(b)); return r;
}
__device__ __forceinline__ float2 unpack2f(unsigned long long v) {
    float2 r; asm("mov.b64 {%0, %1}, %2;" : "=f"(r.x), "=f"(r.y) : "l"(v)); return r;
}
__device__ __forceinline__ void ffma2(unsigned long long &acc, unsigned long long a, unsigned long long b) {
    asm("fma.rn.f32x2 %0, %1, %2, %0;" : "+l"(acc) : "l"(a), "l"(b));
}
__device__ __forceinline__ unsigned mono(float f) {
    unsigned u = __float_as_uint(f); return (u & 0x80000000u) ? ~u : (u | 0x80000000u);
}
__device__ __forceinline__ float invmono(unsigned u) {
    unsigned v = (u & 0x80000000u) ? (u & 0x7FFFFFFFu) : ~u; return __uint_as_float(v);
}
__device__ __forceinline__ float gelu_tanh(float x) {
    float g = 0.7978845608028654f * x * fmaf(0.044715f, x * x, 1.0f);
    float e = __expf(2.0f * g);
    return 0.5f * x * (2.0f - 2.0f / (e + 1.0f));
}
__device__ __forceinline__ uint32_t cvt_tf32(float f) {
    uint32_t r; asm("cvt.rna.tf32.f32 %0, %1;" : "=r"(r) : "f"(f)); return r;
}
__device__ __forceinline__ void mma_tf32(float* d, const uint32_t* a, const uint32_t* b) {
    asm volatile("mma.sync.aligned.m16n8k8.row.col.f32.tf32.tf32.f32 "
                 "{%0,%1,%2,%3}, {%4,%5,%6,%7}, {%8,%9}, {%0,%1,%2,%3};"
                 : "+f"(d[0]), "+f"(d[1]), "+f"(d[2]), "+f"(d[3])
                 : "r"(a[0]), "r"(a[1]), "r"(a[2]), "r"(a[3]), "r"(b[0]), "r"(b[1]));
}

// ---- transpose [R,C]->[C,R] per batch ----
template<int R, int C, int WHICH>
__global__ void k_transpose(const float* __restrict__ src) {
    float* dstbase = (WHICH == 0) ? g_coorT : (WHICH == 1) ? g_spT : g_wspT;
    __shared__ float tile[32][33];
    int b = blockIdx.z;
    const float* s = src + (size_t)b * R * C;
    float* d = dstbase + (size_t)b * R * C;
    int r0 = blockIdx.y * 32, c0 = blockIdx.x * 32;
#pragma unroll
    for (int k = 0; k < 32; k += 8)
        tile[threadIdx.y + k][threadIdx.x] = s[(size_t)(r0 + threadIdx.y + k) * C + c0 + threadIdx.x];
    __syncthreads();
#pragma unroll
    for (int k = 0; k < 32; k += 8)
        d[(size_t)(c0 + threadIdx.y + k) * R + r0 + threadIdx.x] = tile[threadIdx.x][threadIdx.y + k];
}

template<int WHICH>
__global__ void k_norm128(const float* __restrict__ src, int rows) {
    float* dst = WHICH ? g_normB : g_normM;
    int warp = (blockIdx.x * blockDim.x + threadIdx.x) >> 5, lane = threadIdx.x & 31;
    if (warp >= rows) return;
    float4 v = ((const float4*)(src + (size_t)warp * 128))[lane];
    float s = v.x * v.x + v.y * v.y + v.z * v.z + v.w * v.w;
#pragma unroll
    for (int off = 16; off; off >>= 1) s += __shfl_xor_sync(0xffffffffu, s, off);
    if (!lane) dst[warp] = s;
}

// ---- top-2 neighbors ----
__global__ __launch_bounds__(256) void k_topk(const float* __restrict__ bef) {
    __shared__ float befs[16 * 128];
    __shared__ unsigned long long red[8];
    __shared__ unsigned long long s_win;
    int n0 = blockIdx.x * 16, b = blockIdx.y, tid = threadIdx.x;
    for (int idx = tid; idx < 16 * 128; idx += 256)
        befs[idx] = bef[((size_t)b * N_BEF + n0) * 128 + idx];
    __syncthreads();
    int m = tid;
    float acc[16];
#pragma unroll
    for (int j = 0; j < 16; j++) acc[j] = 0.0f;
    const float* cT = g_coorT + (size_t)b * 128 * N_STK + m;
    for (int cb = 0; cb < 128; cb += 32) {
        float part[16];
#pragma unroll
        for (int j = 0; j < 16; j++) part[j] = 0.0f;
        for (int c0 = cb; c0 < cb + 32; c0 += 4) {
            float v0 = cT[(c0 + 0) * N_STK], v1 = cT[(c0 + 1) * N_STK];
            float v2 = cT[(c0 + 2) * N_STK], v3 = cT[(c0 + 3) * N_STK];
#pragma unroll
            for (int j = 0; j < 16; j++) {
                float4 bf = *(const float4*)&befs[j * 128 + c0];
                part[j] = fmaf(bf.x, v0, part[j]); part[j] = fmaf(bf.y, v1, part[j]);
                part[j] = fmaf(bf.z, v2, part[j]); part[j] = fmaf(bf.w, v3, part[j]);
            }
        }
#pragma unroll
        for (int j = 0; j < 16; j++) acc[j] += part[j];
    }
    float nm = g_normM[b * N_STK + m];
    int lane = tid & 31, wid = tid >> 5;
    for (int j = 0; j < 16; j++) {
        float d2v = g_normB[b * N_BEF + n0 + j] + nm - 2.0f * acc[j];
        unsigned long long key = ((unsigned long long)mono(d2v) << 8) | (unsigned)m;
        unsigned long long k = key;
#pragma unroll
        for (int off = 16; off; off >>= 1) { unsigned long long o = __shfl_xor_sync(0xffffffffu, k, off); if (o < k) k = o; }
        if (lane == 0) red[wid] = k;
        __syncthreads();
        if (tid == 0) { unsigned long long mn = red[0];
#pragma unroll
            for (int w = 1; w < 8; w++) if (red[w] < mn) mn = red[w];
            s_win = mn; }
        __syncthreads();
        unsigned long long win1 = s_win;
        k = (key == win1) ? 0xFFFFFFFFFFFFFFFFull : key;
#pragma unroll
        for (int off = 16; off; off >>= 1) { unsigned long long o = __shfl_xor_sync(0xffffffffu, k, off); if (o < k) k = o; }
        if (lane == 0) red[wid] = k;
        __syncthreads();
        if (tid == 0) {
            unsigned long long mn2 = red[0];
#pragma unroll
            for (int w = 1; w < 8; w++) if (red[w] < mn2) mn2 = red[w];
            float d0 = invmono((unsigned)(win1 >> 8)), d1 = invmono((unsigned)(mn2 >> 8));
            float r0 = 1.0f / (d0 + 1e-8f), r1 = 1.0f / (d1 + 1e-8f), s = r0 + r1;
            g_nn[b * N_BEF + n0 + j] = make_int2((int)(win1 & 0xFF), (int)(mn2 & 0xFF));
            g_wt[b * N_BEF + n0 + j] = make_float2(r0 / s, r1 / s);
        }
        __syncthreads();
    }
}

// ---- sparse branch ----
__global__ __launch_bounds__(256) void k_sparse(const float* __restrict__ b_sp,
                                                const float* __restrict__ gam,
                                                const float* __restrict__ bet,
                                                float* __restrict__ out) {
    __shared__ float V[512 * 20];
    __shared__ int2 ii[16];
    __shared__ float2 ww[16];
    int n0 = blockIdx.x * 16, b = blockIdx.y, tid = threadIdx.x;
    if (tid < 16) { ii[tid] = g_nn[b * N_BEF + n0 + tid]; ww[tid] = g_wt[b * N_BEF + n0 + tid]; }
    __syncthreads();
    const float* sT = g_spT + (size_t)b * N_STK * SP_IN;
    for (int idx = tid; idx < 512 * 16; idx += 256) {
        int j = idx >> 9, c = idx & 511;
        int2 id = ii[j]; float2 wt = ww[j];
        V[c * 20 + j] = wt.x * sT[(size_t)id.x * SP_IN + c] + wt.y * sT[(size_t)id.y * SP_IN + c];
    }
    __syncthreads();
    int o = tid;
    unsigned long long acc[8] = {0,0,0,0,0,0,0,0};
#pragma unroll 4
    for (int c = 0; c < 512; c++) {
        float wv = g_wspT[c * SP_OUT + o];
        unsigned long long w2 = pack2(wv, wv);
        const ulonglong2* vr = (const ulonglong2*)&V[c * 20];
        ulonglong2 p0 = vr[0], p1 = vr[1], p2 = vr[2], p3 = vr[3];
        ffma2(acc[0], w2, p0.x); ffma2(acc[1], w2, p0.y);
        ffma2(acc[2], w2, p1.x); ffma2(acc[3], w2, p1.y);
        ffma2(acc[4], w2, p2.x); ffma2(acc[5], w2, p2.y);
        ffma2(acc[6], w2, p3.x); ffma2(acc[7], w2, p3.y);
    }
    float bias = b_sp[o], sc = gam[o] * INV_SQRT_BN, bt = bet[o];
    float res[16];
#pragma unroll
    for (int p = 0; p < 8; p++) {
        float2 f = unpack2f(acc[p]);
        res[2 * p] = gelu_tanh(fmaf(f.x + bias, sc, bt));
        res[2 * p + 1] = gelu_tanh(fmaf(f.y + bias, sc, bt));
    }
    float* ob = out + ((size_t)b * SP_OUT + o) * N_BEF + n0;
#pragma unroll
    for (int q = 0; q < 4; q++)
        *(float4*)&ob[4 * q] = make_float4(res[4 * q], res[4 * q + 1], res[4 * q + 2], res[4 * q + 3]);
}

// ---- prep A: fragment-ordered tf32 tap images ----
// layout: [par][ ((s*8+mt)*32 + lane)*4 + r ], r = a0..a3 of m16n8k8
__global__ void k_prepA(const float* __restrict__ w_ct) {
    int idx = blockIdx.x * 256 + threadIdx.x;   // 0..65535
    int par = idx >> 15, rem = idx & 32767;
    int s = rem >> 10, mt = (rem >> 7) & 7, lane = (rem >> 2) & 31, r = rem & 3;
    int g = lane >> 2, tg = lane & 3;
    int m = mt * 16 + g + ((r & 1) ? 8 : 0);
    int k = s * 8 + tg + ((r >= 2) ? 4 : 0);
    int c = k >> 1, q = k & 1;
    int tap = par ? (q ? 0 : 2) : (q ? 1 : 3);
    g_Afrag[par * 32768 + rem] = __uint_as_float(cvt_tf32(w_ct[c * 512 + m * 4 + tap]));
}

// ---- prep Dp: interpolated transposed sequence with edge pad ----
__global__ __launch_bounds__(256) void k_prepD(const float* __restrict__ dense) {
    __shared__ float sm[128 * 33];
    int n = blockIdx.x, b = blockIdx.y, tid = threadIdx.x;
    int2 id = g_nn[b * N_BEF + n]; float2 wt = g_wt[b * N_BEF + n];
    const float* dB = dense + (size_t)b * DN_IN * 8192;
    int w = tid >> 5, p = tid & 31;
    for (int c = w; c < 128; c += 8)
        sm[c * 33 + p] = wt.x * dB[c * 8192 + id.x * 32 + p] + wt.y * dB[c * 8192 + id.y * 32 + p];
    __syncthreads();
    float* Dp = g_Dp + ((size_t)b * 16386 + 1 + n * 32) * 128;
    for (int i = tid; i < 32 * 128; i += 256) Dp[i] = sm[(i & 127) * 33 + (i >> 7)];
    if (n == 0)   for (int i = tid; i < 128; i += 256) g_Dp[(size_t)b * 16386 * 128 + i] = sm[i * 33];
    if (n == 511) for (int i = tid; i < 128; i += 256) g_Dp[((size_t)b * 16386 + 16385) * 128 + i] = sm[i * 33 + 31];
}

// ---- dense GEMM via mma.sync tf32 (persistent, parity per CTA pair) ----
#define STG_STRIDE 132
#define SMEM_FLOATS (32768 + 66 * STG_STRIDE)   // A frags + stage
__global__ void __launch_bounds__(256, 1) k_gemm(const float* __restrict__ b_ct,
                                                 const float* __restrict__ gam,
                                                 const float* __restrict__ bet,
                                                 float* __restrict__ out) {
    extern __shared__ float sf[];
    float* Af = sf;
    float* stg = sf + 32768;
    int tid = threadIdx.x, wid = tid >> 5, lane = tid & 31;
    int warpM = wid & 3, warpN = wid >> 2;
    int g = lane >> 2, r4 = lane & 3;
    int par = blockIdx.x & 1, cpair = blockIdx.x >> 1;

    // resident A image (fragment order)
    const float4* Ag = (const float4*)(g_Afrag + par * 32768);
    float4* Af4 = (float4*)Af;
    for (int i = tid; i < 8192; i += 256) Af4[i] = Ag[i];

    // epilogue constants for this thread's 4 output rows
    float bs_[2][2], sc_[2][2], bt_[2][2];
#pragma unroll
    for (int mt = 0; mt < 2; mt++)
#pragma unroll
        for (int hh = 0; hh < 2; hh++) {
            int o = warpM * 32 + mt * 16 + g + hh * 8;
            bs_[mt][hh] = b_ct[o];
            sc_[mt][hh] = gam[o] * INV_SQRT_BN;
            bt_[mt][hh] = bet[o];
        }
    // per-nt B row bases (row = n + par + q, constant across tiles/s)
    int q = r4 & 1, ch = r4 >> 1;
    int rowb[4];
#pragma unroll
    for (int nt = 0; nt < 4; nt++)
        rowb[nt] = (warpN * 32 + nt * 8 + g + par + q) * STG_STRIDE;
    __syncthreads();

    for (int T = cpair; T < 4096; T += 74) {
        int b = T >> 8, j0 = (T & 255) << 6;
        // stage 66 rows of g_Dp
        const float4* src = (const float4*)(g_Dp + ((size_t)b * 16386 + j0) * 128);
        for (int i = tid; i < 66 * 32; i += 256) {
            int r = i >> 5, c4 = i & 31;
            *(float4*)&stg[r * STG_STRIDE + c4 * 4] = src[r * 32 + c4];
        }
        __syncthreads();

        float acc[2][4][4];
#pragma unroll
        for (int mt = 0; mt < 2; mt++)
#pragma unroll
            for (int nt = 0; nt < 4; nt++)
#pragma unroll
                for (int r = 0; r < 4; r++) acc[mt][nt][r] = 0.0f;

#pragma unroll 4
        for (int s = 0; s < 32; s++) {
            uint32_t a[2][4];
            *(float4*)a[0] = Af4[(s * 8 + warpM * 2 + 0) * 32 + lane];
            *(float4*)a[1] = Af4[(s * 8 + warpM * 2 + 1) * 32 + lane];
            uint32_t bf[4][2];
#pragma unroll
            for (int nt = 0; nt < 4; nt++) {
                float4 v = *(const float4*)&stg[rowb[nt] + 4 * s];
                bf[nt][0] = cvt_tf32(ch ? v.y : v.x);
                bf[nt][1] = cvt_tf32(ch ? v.w : v.z);
            }
#pragma unroll
            for (int mt = 0; mt < 2; mt++)
#pragma unroll
                for (int nt = 0; nt < 4; nt++)
                    mma_tf32(acc[mt][nt], a[mt], bf[nt]);
        }

        // epilogue: bias + BN + GELU, interleaved parity stores
        float* ob = out + ((size_t)b * 128 + warpM * 32 + g) * 32768 + par;
        int jbase = j0 + warpN * 32 + r4 * 2;
#pragma unroll
        for (int mt = 0; mt < 2; mt++)
#pragma unroll
            for (int nt = 0; nt < 4; nt++) {
                float* p0 = ob + (size_t)(mt * 16) * 32768 + 2 * (jbase + nt * 8);
                float* p1 = p0 + (size_t)8 * 32768;
                p0[0] = gelu_tanh(fmaf(acc[mt][nt][0] + bs_[mt][0], sc_[mt][0], bt_[mt][0]));
                p0[2] = gelu_tanh(fmaf(acc[mt][nt][1] + bs_[mt][0], sc_[mt][0], bt_[mt][0]));
                p1[0] = gelu_tanh(fmaf(acc[mt][nt][2] + bs_[mt][1], sc_[mt][1], bt_[mt][1]));
                p1[2] = gelu_tanh(fmaf(acc[mt][nt][3] + bs_[mt][1], sc_[mt][1], bt_[mt][1]));
            }
        __syncthreads();
    }
}

// ---- launcher ----
extern "C" void kernel_launch(void* const* d_in, const int* in_sizes, int n_in,
                              void* d_out, int out_size) {
    const float* sparse_fea = (const float*)d_in[0];
    const float* dense_fea  = (const float*)d_in[1];
    const float* stk_coor   = (const float*)d_in[2];
    const float* stk_bef    = (const float*)d_in[3];
    const float* w_sp  = (const float*)d_in[4];
    const float* b_sp  = (const float*)d_in[5];
    const float* g_sp  = (const float*)d_in[6];
    const float* be_sp = (const float*)d_in[7];
    const float* w_ct  = (const float*)d_in[8];
    const float* b_ct  = (const float*)d_in[9];
    const float* g_dn  = (const float*)d_in[10];
    const float* be_dn = (const float*)d_in[11];
    float* out_sp = (float*)d_out;
    float* out_dn = out_sp + (size_t)BS * SP_OUT * N_BEF;

    static bool attr_set = false;
    if (!attr_set) {
        cudaFuncSetAttribute(k_gemm, cudaFuncAttributeMaxDynamicSharedMemorySize,
                             SMEM_FLOATS * sizeof(float));
        attr_set = true;
    }
    k_transpose<256, 128, 0><<<dim3(4, 8, 16), dim3(32, 8)>>>(stk_coor);
    k_transpose<512, 256, 1><<<dim3(8, 16, 16), dim3(32, 8)>>>(sparse_fea);
    k_transpose<256, 512, 2><<<dim3(16, 8, 1), dim3(32, 8)>>>(w_sp);
    k_norm128<0><<<512, 256>>>(stk_coor, BS * N_STK);
    k_norm128<1><<<1024, 256>>>(stk_bef, BS * N_BEF);
    k_topk<<<dim3(32, 16), 256>>>(stk_bef);
    k_prepA<<<256, 256>>>(w_ct);
    k_prepD<<<dim3(512, 16), 256>>>(dense_fea);
    k_sparse<<<dim3(32, 16), 256>>>(b_sp, g_sp, be_sp, out_sp);
    k_gemm<<<148, 256, SMEM_FLOATS * sizeof(float)>>>(b_ct, g_dn, be_dn, out_dn);
}